// round 13
// baseline (speedup 1.0000x reference)
#include <cuda_runtime.h>
#include <cuda_bf16.h>
#include <cstdint>

#define B_IMG 128
#define B_CAP 128
#define R 64
#define W 64
#define D 128

// Operand tiles: bf16 pairs packed in u32, pitch 68 (68 mod 32 = 4):
// ldmatrix 8-row phases cover banks 4r..4r+3 -> all 32 banks -> conflict-free.
#define OP_PITCH 68
#define OP_TILE  (64 * OP_PITCH)     // 4352 u32 per operand tile (3 tiles = 13056)
#define S_PITCH  68                  // sims pitch: float4 row loads conflict-free
#define SS_T     (64 * S_PITCH)      // 4352 floats per sims tile
// sims: 2 row-major tiles (8704 floats) overlay the operand region (13056)
#define SMEM_U32   (3 * OP_TILE + 256)
#define SMEM_BYTES (SMEM_U32 * 4)    // 53,248 B -> 4 CTAs/SM (213 KB <= 228 KB)

__device__ __forceinline__ uint32_t pack_bf16x2(float lo, float hi) {
    __nv_bfloat162 h = __float22bfloat162_rn(make_float2(lo, hi)); // .x = low half
    return *(uint32_t*)&h;
}

__device__ __forceinline__ uint32_t s2u(const void* p) {
    return (uint32_t)__cvta_generic_to_shared(p);
}

#define LDSM_X4(r, addr)                                                      \
    asm volatile("ldmatrix.sync.aligned.m8n8.x4.shared.b16 {%0,%1,%2,%3}, [%4];" \
        : "=r"((r)[0]), "=r"((r)[1]), "=r"((r)[2]), "=r"((r)[3]) : "r"(addr))

#define MMA_BF16(d, a, b)                                                     \
    asm volatile(                                                             \
        "mma.sync.aligned.m16n8k16.row.col.f32.bf16.bf16.f32 "                \
        "{%0,%1,%2,%3}, {%4,%5,%6,%7}, {%8,%9}, {%0,%1,%2,%3};\n"             \
        : "+f"(d[0]), "+f"(d[1]), "+f"(d[2]), "+f"(d[3])                      \
        : "r"((a)[0]), "r"((a)[1]), "r"((a)[2]), "r"((a)[3]),                 \
          "r"((b)[0]), "r"((b)[1]))

// One CTA = 1 image x 2 captions. 256 threads, 64-reg target -> 4 CTAs/SM.
__global__ __launch_bounds__(256, 4) void select_kernel(
    const float* __restrict__ imgs, const float* __restrict__ caps,
    const int* __restrict__ img_lens, const int* __restrict__ cap_lens,
    float* __restrict__ out)
{
    extern __shared__ uint32_t smu[];
    float* smf = (float*)smu;
    uint32_t* As  = smu;                 // [64][OP_PITCH] bf16x2 imgs tile
    uint32_t* Bs0 = smu + OP_TILE;       // caps tile pair 0 (pair 1 at +OP_TILE)
    float*    red = smf + 3 * OP_TILE;   // [256]

    const int i   = blockIdx.y;
    const int t0  = blockIdx.x * 2;
    const int tid = threadIdx.x;

    const int nv  = __ldg(img_lens + i);
    const int nt0 = __ldg(cap_lens + t0);
    const int nt1 = __ldg(cap_lens + t0 + 1);

    // ---- Phase 1: coalesced float4 load -> bf16x2 pack -> padded smem ----
    {
        const float4* gi = (const float4*)(imgs + (size_t)i * R * D);
        const float4* gc = (const float4*)(caps + (size_t)t0 * W * D);
        #pragma unroll
        for (int j = tid; j < R * D / 4; j += 256) {
            float4 v = gi[j];
            int row = j >> 5, cu = (j & 31) << 1;      // u32 column
            uint2 w;
            w.x = pack_bf16x2(v.x, v.y);
            w.y = pack_bf16x2(v.z, v.w);
            *(uint2*)(As + row * OP_PITCH + cu) = w;
        }
        #pragma unroll
        for (int j = tid; j < 2 * W * D / 4; j += 256) {
            float4 v = gc[j];
            int p = j >> 11;
            int jj = j & 2047;
            int row = jj >> 5, cu = (jj & 31) << 1;
            uint2 w;
            w.x = pack_bf16x2(v.x, v.y);
            w.y = pack_bf16x2(v.z, v.w);
            *(uint2*)(Bs0 + p * OP_TILE + row * OP_PITCH + cu) = w;
        }
    }
    __syncthreads();

    // ---- Phase 2: per pair 64x64x128 GEMM, ldmatrix.x4 fragment loads ----
    {
        const int warp = tid >> 5;
        const int lane = tid & 31;
        const int p    = warp >> 2;
        const int w4   = warp & 3;
        const int g    = lane >> 2;
        const int t4   = lane & 3;
        const int warpM = (w4 >> 1) * 32;
        const int warpN = (w4 & 1) * 32;
        const uint32_t* Bp = Bs0 + p * OP_TILE;
        const int   ntp = p ? nt1 : nt0;

        const int l7  = lane & 7;
        const int l8  = (lane >> 3) & 1;
        const int l16 = (lane >> 4) & 1;

        uint32_t aAddr = s2u(As + (warpM + l7 + 8 * l8) * OP_PITCH + 4 * l16);
        uint32_t bAddr = s2u(Bp + (warpN + l7 + 8 * l16) * OP_PITCH + 4 * l8);
        const uint32_t rowStep16 = 16 * OP_PITCH * 4;   // +16 rows, bytes

        float acc[2][4][4];
        #pragma unroll
        for (int mi = 0; mi < 2; ++mi)
            #pragma unroll
            for (int ni = 0; ni < 4; ++ni)
                #pragma unroll
                for (int q = 0; q < 4; ++q) acc[mi][ni][q] = 0.0f;

        #pragma unroll
        for (int kb = 0; kb < 8; ++kb) {         // 8 k-blocks of 16
            uint32_t a[2][4], b[2][4];
            LDSM_X4(a[0], aAddr + kb * 32);
            LDSM_X4(a[1], aAddr + rowStep16 + kb * 32);
            LDSM_X4(b[0], bAddr + kb * 32);
            LDSM_X4(b[1], bAddr + rowStep16 + kb * 32);
            #pragma unroll
            for (int mi = 0; mi < 2; ++mi) {
                #pragma unroll
                for (int nq = 0; nq < 2; ++nq) {
                    MMA_BF16(acc[mi][2 * nq],     a[mi], b[nq]);      // n octet 0
                    MMA_BF16(acc[mi][2 * nq + 1], a[mi], b[nq] + 2);  // n octet 1
                }
            }
        }

        __syncthreads();   // operands dead; sims tiles overlay them

        // epilogue: PRE-SHIFTED sims z' = sims + 256 (masked -> exactly 255),
        // single row-major store per pair.
        float* Sp = smf + p * SS_T;
        #pragma unroll
        for (int mi = 0; mi < 2; ++mi) {
            #pragma unroll
            for (int ni = 0; ni < 4; ++ni) {
                int r0 = warpM + mi * 16 + g;
                int r1 = r0 + 8;
                int c0 = warpN + ni * 8 + 2 * t4;
                bool cv0 = (c0 < ntp), cv1 = (c0 + 1 < ntp);
                float v00 = (r0 < nv && cv0) ? acc[mi][ni][0] + 256.0f : 255.0f;
                float v01 = (r0 < nv && cv1) ? acc[mi][ni][1] + 256.0f : 255.0f;
                float v10 = (r1 < nv && cv0) ? acc[mi][ni][2] + 256.0f : 255.0f;
                float v11 = (r1 < nv && cv1) ? acc[mi][ni][3] + 256.0f : 255.0f;
                *(float2*)(Sp + r0 * S_PITCH + c0) = make_float2(v00, v01);
                *(float2*)(Sp + r1 * S_PITCH + c0) = make_float2(v10, v11);
            }
        }
    }
    __syncthreads();

    // ---- Phase 3: sparsemax. z[0..47] in regs, tail 16 re-read from smem ----
    // tid layout: [pair(1)][role(1)][r(6)]; role 0 = region rows, role 1 = word cols
    {
        const int p    = tid >> 7;
        const int role = (tid >> 6) & 1;
        const int r    = tid & 63;
        const int ntp  = p ? nt1 : nt0;
        const int m    = role ? nv : ntp;      // valid elements (warp-uniform)
        float* Sp = smf + p * SS_T;

        float z[48];
        if (role == 0) {
            const float4* b4 = (const float4*)(Sp + r * S_PITCH);
            #pragma unroll
            for (int j = 0; j < 12; ++j) {
                float4 v = b4[j];
                z[4 * j]     = v.x; z[4 * j + 1] = v.y;
                z[4 * j + 2] = v.z; z[4 * j + 3] = v.w;
            }
        } else {
            #pragma unroll
            for (int j = 0; j < 48; ++j) z[j] = Sp[j * S_PITCH + r];
        }

        // total shifted sum S over all 64 (tail read from smem)
        float s0 = 0.f, s1 = 0.f, s2 = 0.f, s3 = 0.f;
        #pragma unroll
        for (int j = 0; j < 48; j += 4) {
            s0 += z[j]; s1 += z[j + 1]; s2 += z[j + 2]; s3 += z[j + 3];
        }
        if (role == 0) {
            const float4* t4p = (const float4*)(Sp + r * S_PITCH + 48);
            #pragma unroll
            for (int j = 0; j < 4; ++j) {
                float4 v = t4p[j];
                s0 += v.x; s1 += v.y; s2 += v.z; s3 += v.w;
            }
        } else {
            #pragma unroll
            for (int j = 0; j < 16; ++j)
                s0 += Sp[(48 + j) * S_PITCH + r];
        }
        const float S = (s0 + s1) + (s2 + s3);

        // analytic init: support = valid set (masked entries sit at exactly 255)
        float kprev = (float)m;
        float tau = __fdividef(S - (float)(64 - m) * 255.0f - 1.0f, kprev);
        if (!(tau > 255.0f)) {                  // rare: support includes masked
            tau = (S - 1.0f) * (1.0f / 64.0f);
            kprev = 64.0f;
        }

        // Michelot, joint sum+count accumulator: q = sum + 256*count
        float qf = kprev * tau + 1.0f;
        float kf = kprev;
        #pragma unroll 1
        for (int it = 0; it < 24; ++it) {
            float q0 = 0.f, q1 = 0.f, q2 = 0.f, q3 = 0.f;
            #pragma unroll
            for (int j = 0; j < 48; j += 4) {
                if (z[j]     > tau) q0 += z[j];
                if (z[j + 1] > tau) q1 += z[j + 1];
                if (z[j + 2] > tau) q2 += z[j + 2];
                if (z[j + 3] > tau) q3 += z[j + 3];
            }
            if (role == 0) {                    // warp-uniform branch
                const float4* t4p = (const float4*)(Sp + r * S_PITCH + 48);
                #pragma unroll
                for (int j = 0; j < 4; ++j) {
                    float4 v = t4p[j];
                    if (v.x > tau) q0 += v.x;
                    if (v.y > tau) q1 += v.y;
                    if (v.z > tau) q2 += v.z;
                    if (v.w > tau) q3 += v.w;
                }
            } else {
                #pragma unroll
                for (int j = 0; j < 16; ++j) {
                    float v = Sp[(48 + j) * S_PITCH + r];
                    if (v > tau) q0 += v;
                }
            }
            qf = (q0 + q1) + (q2 + q3);
            kf = rintf(qf * 0.00390625f);       // exact count: |sum sims| <= 64 < 128
            bool done = (kf == kprev);
            if (__all_sync(0xffffffffu, done)) break;
            if (!done) {
                kprev = kf;
                tau = __fdividef(qf - 1.0f, kf);
            }
        }

        // rsum = sum relu(z'-tau')^2 + (tau'-256) * sum relu(z'-tau')
        float a0 = 0.f, a1 = 0.f, a2 = 0.f, a3 = 0.f;
        #pragma unroll
        for (int j = 0; j < 48; j += 4) {
            float p0 = fmaxf(z[j]     - tau, 0.f);
            float p1 = fmaxf(z[j + 1] - tau, 0.f);
            float p2 = fmaxf(z[j + 2] - tau, 0.f);
            float p3 = fmaxf(z[j + 3] - tau, 0.f);
            a0 = fmaf(p0, p0, a0);
            a1 = fmaf(p1, p1, a1);
            a2 = fmaf(p2, p2, a2);
            a3 = fmaf(p3, p3, a3);
        }
        if (role == 0) {
            const float4* t4p = (const float4*)(Sp + r * S_PITCH + 48);
            #pragma unroll
            for (int j = 0; j < 4; ++j) {
                float4 v = t4p[j];
                float p0 = fmaxf(v.x - tau, 0.f);
                float p1 = fmaxf(v.y - tau, 0.f);
                float p2 = fmaxf(v.z - tau, 0.f);
                float p3 = fmaxf(v.w - tau, 0.f);
                a0 = fmaf(p0, p0, a0);
                a1 = fmaf(p1, p1, a1);
                a2 = fmaf(p2, p2, a2);
                a3 = fmaf(p3, p3, a3);
            }
        } else {
            #pragma unroll
            for (int j = 0; j < 16; ++j) {
                float v = Sp[(48 + j) * S_PITCH + r];
                float p0 = fmaxf(v - tau, 0.f);
                a0 = fmaf(p0, p0, a0);
            }
        }
        float sp   = qf - kf * tau;             // sum of (z'-tau') over support
        float rsum = ((a0 + a1) + (a2 + a3)) + (tau - 256.0f) * sp;

        bool valid = role ? (r < ntp) : (r < nv);
        red[tid] = valid ? rsum : 0.0f;
    }
    __syncthreads();

    // ---- Phase 4: masked means; warp 0 -> pair 0, warp 1 -> pair 1 ----
    if (tid < 64) {
        const int wp   = tid >> 5;
        const int lane = tid & 31;
        const float* rp = red + wp * 128;
        float v = rp[lane]      + rp[lane + 32];
        float w = rp[64 + lane] + rp[96 + lane];
        #pragma unroll
        for (int o = 16; o; o >>= 1) {
            v += __shfl_down_sync(0xffffffffu, v, o);
            w += __shfl_down_sync(0xffffffffu, w, o);
        }
        if (lane == 0) {
            int nt = wp ? nt1 : nt0;
            out[i * B_CAP + t0 + wp] = 0.5f * (v / (float)nv + w / (float)nt);
        }
    }
}

extern "C" void kernel_launch(void* const* d_in, const int* in_sizes, int n_in,
                              void* d_out, int out_size)
{
    // metadata order: img_cls, imgs, cap_cls, caps, img_lens, cap_lens
    const float* imgs     = (const float*)d_in[1];
    const float* caps     = (const float*)d_in[3];
    const int*   img_lens = (const int*)d_in[4];
    const int*   cap_lens = (const int*)d_in[5];
    float*       out      = (float*)d_out;

    cudaFuncSetAttribute(select_kernel,
                         cudaFuncAttributeMaxDynamicSharedMemorySize, SMEM_BYTES);

    dim3 grid(B_CAP / 2, B_IMG);
    select_kernel<<<grid, 256, SMEM_BYTES>>>(imgs, caps, img_lens, cap_lens, out);
}

// round 15
// speedup vs baseline: 1.3409x; 1.3409x over previous
#include <cuda_runtime.h>
#include <cuda_bf16.h>
#include <cstdint>

#define B_IMG 128
#define B_CAP 128
#define R 64
#define W 64
#define D 128

// Operand tiles: bf16 pairs packed in u32, pitch 68 (68 mod 32 = 4):
// ldmatrix 8-row phases cover banks 4r..4r+3 -> all 32 banks -> conflict-free.
#define OP_PITCH 68
#define OP_TILE  (64 * OP_PITCH)     // 4352 u32 per operand tile (3 tiles = 13056)
#define S_PITCH  68                  // sims pitch: float4 row loads conflict-free
#define SS_T     (64 * S_PITCH)      // 4352 floats per sims tile
// sims: 4 tiles (row p0, row p1, T p0, T p1) = 17408 floats, overlaying operands
#define SMEM_U32   (4 * SS_T + 256)
#define SMEM_BYTES (SMEM_U32 * 4)    // 70,656 B -> 3 CTAs/SM (212 KB <= 228 KB)

// bf16 scratch: inputs converted ONCE by a pre-pass kernel (graph has 2 launches).
// Layout: per image/caption, 64 rows x 32 uint2 (= 64 u32 = 128 bf16), row-major.
__device__ uint2 g_imgs_bf[B_IMG * R * D / 4];   // 262144 uint2 = 2 MB
__device__ uint2 g_caps_bf[B_CAP * W * D / 4];   // 2 MB

__device__ __forceinline__ uint32_t pack_bf16x2(float lo, float hi) {
    __nv_bfloat162 h = __float22bfloat162_rn(make_float2(lo, hi)); // .x = low half
    return *(uint32_t*)&h;
}

__global__ __launch_bounds__(256) void convert_kernel(
    const float* __restrict__ imgs, const float* __restrict__ caps)
{
    int j = blockIdx.x * 256 + threadIdx.x;      // one float4 per tensor per thread
    float4 a = ((const float4*)imgs)[j];
    g_imgs_bf[j] = make_uint2(pack_bf16x2(a.x, a.y), pack_bf16x2(a.z, a.w));
    float4 b = ((const float4*)caps)[j];
    g_caps_bf[j] = make_uint2(pack_bf16x2(b.x, b.y), pack_bf16x2(b.z, b.w));
}

__device__ __forceinline__ uint32_t s2u(const void* p) {
    return (uint32_t)__cvta_generic_to_shared(p);
}

#define LDSM_X4(r, addr)                                                      \
    asm volatile("ldmatrix.sync.aligned.m8n8.x4.shared.b16 {%0,%1,%2,%3}, [%4];" \
        : "=r"((r)[0]), "=r"((r)[1]), "=r"((r)[2]), "=r"((r)[3]) : "r"(addr))

#define MMA_BF16(d, a, b)                                                     \
    asm volatile(                                                             \
        "mma.sync.aligned.m16n8k16.row.col.f32.bf16.bf16.f32 "                \
        "{%0,%1,%2,%3}, {%4,%5,%6,%7}, {%8,%9}, {%0,%1,%2,%3};\n"             \
        : "+f"(d[0]), "+f"(d[1]), "+f"(d[2]), "+f"(d[3])                      \
        : "r"((a)[0]), "r"((a)[1]), "r"((a)[2]), "r"((a)[3]),                 \
          "r"((b)[0]), "r"((b)[1]))

// One CTA = 1 image x 2 captions. 256 threads.
// Warps 0-3 -> pair 0 GEMM, warps 4-7 -> pair 1 GEMM (each warp 32x32 of 64x64).
__global__ __launch_bounds__(256, 3) void select_kernel(
    const int* __restrict__ img_lens, const int* __restrict__ cap_lens,
    float* __restrict__ out)
{
    extern __shared__ uint32_t smu[];
    float* smf = (float*)smu;
    uint32_t* As  = smu;                 // [64][OP_PITCH] bf16x2 imgs tile
    uint32_t* Bs0 = smu + OP_TILE;       // caps tile pair 0 (pair 1 at +OP_TILE)
    float*    red = smf + 4 * SS_T;      // [256]

    const int i   = blockIdx.y;
    const int t0  = blockIdx.x * 2;
    const int tid = threadIdx.x;

    const int nv  = __ldg(img_lens + i);
    const int nt0 = __ldg(cap_lens + t0);
    const int nt1 = __ldg(cap_lens + t0 + 1);

    // ---- Phase 1: copy pre-converted bf16 into padded smem ----
    {
        const uint2* ga = g_imgs_bf + (size_t)i * (R * D / 4);
        const uint2* gc = g_caps_bf + (size_t)t0 * (W * D / 4);
        #pragma unroll
        for (int j = tid; j < R * D / 4; j += 256) {
            uint2 w = ga[j];
            int row = j >> 5, cu = (j & 31) << 1;      // u32 column
            *(uint2*)(As + row * OP_PITCH + cu) = w;
        }
        #pragma unroll
        for (int j = tid; j < 2 * W * D / 4; j += 256) {
            uint2 w = gc[j];
            int p = j >> 11;
            int jj = j & 2047;
            int row = jj >> 5, cu = (jj & 31) << 1;
            *(uint2*)(Bs0 + p * OP_TILE + row * OP_PITCH + cu) = w;
        }
    }
    __syncthreads();

    // ---- Phase 2: per pair 64x64x128 GEMM, ldmatrix.x4 fragment loads ----
    {
        const int warp = tid >> 5;
        const int lane = tid & 31;
        const int p    = warp >> 2;
        const int w4   = warp & 3;
        const int g    = lane >> 2;
        const int t4   = lane & 3;
        const int warpM = (w4 >> 1) * 32;
        const int warpN = (w4 & 1) * 32;
        const uint32_t* Bp = Bs0 + p * OP_TILE;
        const int   ntp = p ? nt1 : nt0;

        const int l7  = lane & 7;
        const int l8  = (lane >> 3) & 1;
        const int l16 = (lane >> 4) & 1;

        uint32_t aAddr = s2u(As + (warpM + l7 + 8 * l8) * OP_PITCH + 4 * l16);
        uint32_t bAddr = s2u(Bp + (warpN + l7 + 8 * l16) * OP_PITCH + 4 * l8);
        const uint32_t rowStep16 = 16 * OP_PITCH * 4;   // +16 rows, bytes

        float acc[2][4][4];
        #pragma unroll
        for (int mi = 0; mi < 2; ++mi)
            #pragma unroll
            for (int ni = 0; ni < 4; ++ni)
                #pragma unroll
                for (int q = 0; q < 4; ++q) acc[mi][ni][q] = 0.0f;

        #pragma unroll
        for (int kb = 0; kb < 8; ++kb) {         // 8 k-blocks of 16
            uint32_t a[2][4], b[2][4];
            LDSM_X4(a[0], aAddr + kb * 32);
            LDSM_X4(a[1], aAddr + rowStep16 + kb * 32);
            LDSM_X4(b[0], bAddr + kb * 32);
            LDSM_X4(b[1], bAddr + rowStep16 + kb * 32);
            #pragma unroll
            for (int mi = 0; mi < 2; ++mi) {
                #pragma unroll
                for (int nq = 0; nq < 2; ++nq) {
                    MMA_BF16(acc[mi][2 * nq],     a[mi], b[nq]);      // n octet 0
                    MMA_BF16(acc[mi][2 * nq + 1], a[mi], b[nq] + 2);  // n octet 1
                }
            }
        }

        __syncthreads();   // operands dead; sims tiles overlay them

        // epilogue: PRE-SHIFTED sims z' = sims + 256 (masked -> exactly 255),
        // stored twice: row-major (pair tile p) and transposed (tile 2+p).
        float* Sp  = smf + p * SS_T;
        float* SpT = smf + (2 + p) * SS_T;
        #pragma unroll
        for (int mi = 0; mi < 2; ++mi) {
            #pragma unroll
            for (int ni = 0; ni < 4; ++ni) {
                int r0 = warpM + mi * 16 + g;
                int r1 = r0 + 8;
                int c0 = warpN + ni * 8 + 2 * t4;
                bool cv0 = (c0 < ntp), cv1 = (c0 + 1 < ntp);
                float v00 = (r0 < nv && cv0) ? acc[mi][ni][0] + 256.0f : 255.0f;
                float v01 = (r0 < nv && cv1) ? acc[mi][ni][1] + 256.0f : 255.0f;
                float v10 = (r1 < nv && cv0) ? acc[mi][ni][2] + 256.0f : 255.0f;
                float v11 = (r1 < nv && cv1) ? acc[mi][ni][3] + 256.0f : 255.0f;
                *(float2*)(Sp + r0 * S_PITCH + c0) = make_float2(v00, v01);
                *(float2*)(Sp + r1 * S_PITCH + c0) = make_float2(v10, v11);
                SpT[c0 * S_PITCH + r0]       = v00;   // 8t4+g mod 32 distinct
                SpT[(c0 + 1) * S_PITCH + r0] = v01;
                SpT[c0 * S_PITCH + r1]       = v10;
                SpT[(c0 + 1) * S_PITCH + r1] = v11;
            }
        }
    }
    __syncthreads();

    // ---- Phase 3: sparsemax, moment-based init + shifted Michelot ----
    // tid layout: [pair(1)][role(1)][r(6)]; role 0 = region rows, role 1 = word cols
    {
        const int p    = tid >> 7;
        const int role = (tid >> 6) & 1;
        const int r    = tid & 63;
        const int   ntp = p ? nt1 : nt0;
        const int   m   = role ? nv : ntp;      // valid elements in this line
        const float mf  = (float)m;

        const float4* bp =
            (const float4*)(smf + (role * 2 + p) * SS_T + r * S_PITCH);

        float z[64];
        #pragma unroll
        for (int j = 0; j < 16; ++j) {
            float4 v = bp[j];
            z[4 * j] = v.x; z[4 * j + 1] = v.y; z[4 * j + 2] = v.z; z[4 * j + 3] = v.w;
        }

        // load-pass moments: S = sum z', q2c = sum (z'-255.5)^2
        float s0 = 0.f, s1 = 0.f, s2 = 0.f, s3 = 0.f;
        float w0 = 0.f, w1 = 0.f, w2 = 0.f, w3 = 0.f;
        #pragma unroll
        for (int j = 0; j < 64; j += 4) {
            float c0 = z[j]     - 255.5f;
            float c1 = z[j + 1] - 255.5f;
            float c2 = z[j + 2] - 255.5f;
            float c3 = z[j + 3] - 255.5f;
            s0 += z[j]; s1 += z[j + 1]; s2 += z[j + 2]; s3 += z[j + 3];
            w0 = fmaf(c0, c0, w0); w1 = fmaf(c1, c1, w1);
            w2 = fmaf(c2, c2, w2); w3 = fmaf(c3, c3, w3);
        }
        const float S   = (s0 + s1) + (s2 + s3);
        const float q2c = (w0 + w1) + (w2 + w3);

        // analytic lower bound (guaranteed <= tau*): full valid-support iterate
        float kprev = mf;
        float lbtau = __fdividef(S - (float)(64 - m) * 255.0f - 1.0f, mf);
        if (!(lbtau > 255.0f)) {                // rare: support includes masked
            lbtau = (S - 1.0f) * (1.0f / 64.0f);
            kprev = 64.0f;
        }

        // Gaussian-tail model init: tau0 = 255.5 + mu + a*sigma
        float tau;
        {
            float sc   = S - 16320.0f - 0.5f * mf;          // sum of centered valid
            float mu   = sc * __fdividef(1.0f, mf);
            float var  = (q2c - 0.25f * (float)(64 - m)) * __fdividef(1.0f, mf)
                         - mu * mu;
            float sig  = sqrtf(fmaxf(var, 1e-8f));
            float u    = -__logf(fmaxf(mf * sig, 1e-3f));
            u = fminf(fmaxf(u, -6.0f), -0.4f);
            float a = -0.705f + u * (-0.815f + u * (-0.052f));
            a = fminf(fmaxf(a, -0.6f), 2.6f);
            float tau0 = 255.5f + mu + a * sig;
            if (tau0 > lbtau) kprev = -5.0f;    // force at least one scan/update
            else              tau0 = lbtau;
            tau = tau0;
        }

        // Michelot, joint sum+count accumulator: q = sum + 256*count.
        // Uniform loop; overshoot self-corrects (one step lands <= tau*).
        float qf = 0.0f, kf = kprev;
        #pragma unroll 1
        for (int it = 0; it < 24; ++it) {
            float q0 = 0.f, q1 = 0.f, q2 = 0.f, q3 = 0.f;
            #pragma unroll
            for (int j = 0; j < 64; j += 4) {
                if (z[j]     > tau) q0 += z[j];
                if (z[j + 1] > tau) q1 += z[j + 1];
                if (z[j + 2] > tau) q2 += z[j + 2];
                if (z[j + 3] > tau) q3 += z[j + 3];
            }
            qf = (q0 + q1) + (q2 + q3);
            kf = rintf(qf * 0.00390625f);       // exact count: |sum sims| <= 64 < 128
            bool rescue = (kf < 0.5f);          // empty support: init overshot zmax
            bool done   = !rescue && (kf == kprev);
            if (__all_sync(0xffffffffu, done)) break;
            if (!done) {
                if (rescue) { tau = lbtau; kprev = -5.0f; }
                else        { kprev = kf; tau = __fdividef(qf - 1.0f, kf); }
            }
        }

        // rsum = sum_active (z - tau)*z  [unshifted]
        //      = sum relu(z'-tau')^2 + (tau'-256) * sum relu(z'-tau')
        float a0 = 0.f, a1 = 0.f, a2 = 0.f, a3 = 0.f;
        #pragma unroll
        for (int j = 0; j < 64; j += 4) {
            float p0 = fmaxf(z[j]     - tau, 0.f);
            float p1 = fmaxf(z[j + 1] - tau, 0.f);
            float p2 = fmaxf(z[j + 2] - tau, 0.f);
            float p3 = fmaxf(z[j + 3] - tau, 0.f);
            a0 = fmaf(p0, p0, a0);
            a1 = fmaf(p1, p1, a1);
            a2 = fmaf(p2, p2, a2);
            a3 = fmaf(p3, p3, a3);
        }
        float sp   = qf - kf * tau;             // sum of (z'-tau') over support
        float rsum = ((a0 + a1) + (a2 + a3)) + (tau - 256.0f) * sp;

        bool valid = role ? (r < ntp) : (r < nv);
        red[tid] = valid ? rsum : 0.0f;
    }
    __syncthreads();

    // ---- Phase 4: masked means; warp 0 -> pair 0, warp 1 -> pair 1 ----
    if (tid < 64) {
        const int wp   = tid >> 5;
        const int lane = tid & 31;
        const float* rp = red + wp * 128;
        float v = rp[lane]      + rp[lane + 32];
        float w = rp[64 + lane] + rp[96 + lane];
        #pragma unroll
        for (int o = 16; o; o >>= 1) {
            v += __shfl_down_sync(0xffffffffu, v, o);
            w += __shfl_down_sync(0xffffffffu, w, o);
        }
        if (lane == 0) {
            int nt = wp ? nt1 : nt0;
            out[i * B_CAP + t0 + wp] = 0.5f * (v / (float)nv + w / (float)nt);
        }
    }
}

extern "C" void kernel_launch(void* const* d_in, const int* in_sizes, int n_in,
                              void* d_out, int out_size)
{
    // metadata order: img_cls, imgs, cap_cls, caps, img_lens, cap_lens
    const float* imgs     = (const float*)d_in[1];
    const float* caps     = (const float*)d_in[3];
    const int*   img_lens = (const int*)d_in[4];
    const int*   cap_lens = (const int*)d_in[5];
    float*       out      = (float*)d_out;

    cudaFuncSetAttribute(select_kernel,
                         cudaFuncAttributeMaxDynamicSharedMemorySize, SMEM_BYTES);

    // Pre-pass: convert fp32 inputs to bf16 scratch once (1024 * 256 = 262144
    // threads, one float4 per tensor each).
    convert_kernel<<<1024, 256>>>(imgs, caps);

    dim3 grid(B_CAP / 2, B_IMG);
    select_kernel<<<grid, 256, SMEM_BYTES>>>(img_lens, cap_lens, out);
}